// round 2
// baseline (speedup 1.0000x reference)
#include <cuda_runtime.h>

// Fused LRN (all-ones CxC 5x5 filter):
//   s[b,h,w] = sum_c x[b,c,h,w]^2
//   y        = 5x5 zero-padded box sum of s
//   out      = x * (2 + 1e-4*y)^(-0.75)
//
// x: [16, 96, 224, 224] fp32.
//
// One block per (batch, 16x32 spatial tile). The block:
//   1) streams the 20x36 halo across all 96 channels, accumulating s in smem
//      and caching the interior x values in smem (192 KB),
//   2) separable 5x5 box-sum + pow in smem,
//   3) out = smem_x * f  (float4 streaming stores).
// x is read from DRAM exactly once (plus ~27% halo overlap, partly L2-shared);
// out written once. No global scratch.

#define BATCH 16
#define CHAN  96
#define HH    224
#define WW    224
#define HWSZ  (HH * WW)            // 50176
#define CHW   (CHAN * HWSZ)        // 4816896

#define TILE_W 32
#define TILE_H 16
#define TILE_PX (TILE_W * TILE_H)  // 512
#define HALO_W (TILE_W + 4)        // 36
#define HALO_H (TILE_H + 4)        // 20
#define HALO_PX (HALO_W * HALO_H)  // 720

#define NT 512                     // threads per block

// dynamic smem layout (floats):
//   [0,                CHAN*TILE_PX)                    : interior x, [c][lh*32+lw]
//   [CHAN*TILE_PX,     +HALO_PX)                        : s (halo)
//   [...,              +HALO_H*TILE_W)                  : tmp (h-summed)
//   [...,              +TILE_PX)                        : f
#define SM_X_F   (CHAN * TILE_PX)                        // 49152
#define SM_S_OFF (SM_X_F)
#define SM_T_OFF (SM_S_OFF + HALO_PX)
#define SM_F_OFF (SM_T_OFF + HALO_H * TILE_W)
#define SM_TOTAL_F (SM_F_OFF + TILE_PX)                  // 51024 floats
#define SM_BYTES (SM_TOTAL_F * 4)                        // 204096 B

__global__ void __launch_bounds__(NT, 1) lrn_fused_kernel(const float* __restrict__ x,
                                                          float* __restrict__ out) {
    extern __shared__ float sm[];
    float* sm_x = sm;
    float* sm_s = sm + SM_S_OFF;
    float* sm_t = sm + SM_T_OFF;
    float* sm_f = sm + SM_F_OFF;

    const int tid = threadIdx.x;
    const int w0 = blockIdx.x * TILE_W;
    const int h0 = blockIdx.y * TILE_H;
    const int b  = blockIdx.z;
    const float* __restrict__ xb = x + (size_t)b * CHW;

    // ---------------- Phase 1: channel sum-of-squares over halo + cache interior x
    for (int p = tid; p < HALO_PX; p += NT) {
        const int hr = p / HALO_W;           // 0..19
        const int wr = p - hr * HALO_W;      // 0..35
        const int hh = h0 - 2 + hr;
        const int ww = w0 - 2 + wr;
        float acc = 0.f;
        if ((unsigned)hh < HH && (unsigned)ww < WW) {
            const float* __restrict__ xp = xb + hh * WW + ww;
            const int lh = hr - 2;
            const int lw = wr - 2;
            const bool interior = ((unsigned)lh < TILE_H) && ((unsigned)lw < TILE_W);
            float* __restrict__ sxp = sm_x + lh * TILE_W + lw;   // +c*TILE_PX per chan
#pragma unroll 4
            for (int c = 0; c < CHAN; ++c) {
                float v = __ldg(xp + c * HWSZ);
                acc = fmaf(v, v, acc);
                if (interior) sxp[c * TILE_PX] = v;
            }
        }
        sm_s[p] = acc;
    }
    __syncthreads();

    // ---------------- Phase 2: separable 5x5 box sum, then scale factor
    // horizontal: tmp[20][32]
    for (int p = tid; p < HALO_H * TILE_W; p += NT) {
        const int r = p >> 5;                // 0..19
        const int c = p & 31;                // 0..31
        const float* srow = sm_s + r * HALO_W + c;
        sm_t[p] = srow[0] + srow[1] + srow[2] + srow[3] + srow[4];
    }
    __syncthreads();
    // vertical + pow: f[16][32]
    for (int q = tid; q < TILE_PX; q += NT) {
        const int h = q >> 5;
        const int w = q & 31;
        float y = sm_t[h * TILE_W + w] + sm_t[(h + 1) * TILE_W + w] +
                  sm_t[(h + 2) * TILE_W + w] + sm_t[(h + 3) * TILE_W + w] +
                  sm_t[(h + 4) * TILE_W + w];
        float base = fmaf(1e-4f, y, 2.0f);   // in [2, ~3.5): log2f/exp2f safe + accurate
        sm_f[q] = exp2f(-0.75f * log2f(base));
    }
    __syncthreads();

    // ---------------- Phase 3: out = x * f  (float4, streaming stores)
    // 512 threads = 4 channel-groups x 128 float4-pixels.
    const int g  = tid >> 7;                  // 0..3 channel group
    const int q4 = tid & 127;                 // float4 pixel index (covers 512 px)
    const int lh  = q4 >> 3;                  // q4*4 / 32
    const int lw4 = (q4 & 7) << 2;            // (q4*4) % 32

    const float4 fv = reinterpret_cast<const float4*>(sm_f)[q4];
    float* __restrict__ ob = out + (size_t)b * CHW + (h0 + lh) * WW + w0 + lw4;
    const float4* __restrict__ sx4 = reinterpret_cast<const float4*>(sm_x) + q4;

#pragma unroll 4
    for (int c = g; c < CHAN; c += 4) {
        float4 v = sx4[c * (TILE_PX / 4)];
        float4 o;
        o.x = v.x * fv.x;
        o.y = v.y * fv.y;
        o.z = v.z * fv.z;
        o.w = v.w * fv.w;
        __stcs(reinterpret_cast<float4*>(ob + c * HWSZ), o);
    }
}

// ---------------------------------------------------------------------------
extern "C" void kernel_launch(void* const* d_in, const int* in_sizes, int n_in,
                              void* d_out, int out_size) {
    const float* x = (const float*)d_in[0];
    float* out = (float*)d_out;

    static bool attr_set = false;
    if (!attr_set) {
        cudaFuncSetAttribute(lrn_fused_kernel,
                             cudaFuncAttributeMaxDynamicSharedMemorySize, SM_BYTES);
        attr_set = true;
    }

    dim3 grid(WW / TILE_W, HH / TILE_H, BATCH);   // (7, 14, 16) = 1568 blocks
    lrn_fused_kernel<<<grid, NT, SM_BYTES>>>(x, out);
}

// round 5
// speedup vs baseline: 2.2741x; 2.2741x over previous
#include <cuda_runtime.h>

// LRN (all-ones CxC 5x5 filter), L2-chunked 3-kernel pipeline:
//   per 4-batch chunk (77 MB, fits 126 MB L2):
//     A: s_part[half][b,hw] = sum_{c in half} x^2      (x -> L2 resident)
//     B: f = (2 + 1e-4 * boxsum5x5(s0+s1))^-0.75
//     C: out = x * f          (x read back as L2 hits, streaming stores)
//
// x: [16, 96, 224, 224] fp32.

#define BATCH 16
#define CHAN  96
#define HH    224
#define WW    224
#define HWSZ  (HH * WW)            // 50176
#define CHW   (CHAN * HWSZ)        // 4816896

#define CHUNK_B 4                  // batches per chunk (77 MB of x)
#define NCHUNK  (BATCH / CHUNK_B)  // 4
#define CHALF   (CHAN / 2)         // 48

// Scratch (no cudaMalloc allowed).
__device__ float g_sp[2][BATCH * HWSZ];   // per-half channel sum of squares
__device__ float g_f[BATCH * HWSZ];       // final per-pixel scale factor

// ---------------------------------------------------------------------------
// Kernel A: s_part[half][b,hw] = sum over 48 channels of x^2   (float4)
// grid: (chunk_hw4_blocks, 2)   blockIdx.y = channel half
// ---------------------------------------------------------------------------
__global__ void __launch_bounds__(256) chan_sumsq_kernel(const float* __restrict__ x,
                                                         int b0) {
    const int n4 = (CHUNK_B * HWSZ) / 4;
    int i4 = blockIdx.x * blockDim.x + threadIdx.x;
    if (i4 >= n4) return;

    int e  = i4 * 4;
    int lb = e / HWSZ;
    int hw = e - lb * HWSZ;
    int b  = b0 + lb;

    const int half = blockIdx.y;
    const float4* __restrict__ xp =
        reinterpret_cast<const float4*>(x + (size_t)b * CHW + hw) + half * CHALF * (HWSZ / 4);

    float4 acc = make_float4(0.f, 0.f, 0.f, 0.f);
#pragma unroll 8
    for (int c = 0; c < CHALF; ++c) {
        float4 v = __ldg(&xp[c * (HWSZ / 4)]);
        acc.x = fmaf(v.x, v.x, acc.x);
        acc.y = fmaf(v.y, v.y, acc.y);
        acc.z = fmaf(v.z, v.z, acc.z);
        acc.w = fmaf(v.w, v.w, acc.w);
    }
    reinterpret_cast<float4*>(g_sp[half] + (size_t)b * HWSZ + hw)[0] = acc;
}

// ---------------------------------------------------------------------------
// Kernel B: f = (2 + 1e-4 * boxsum5x5(s0+s1))^(-0.75), zero padding.
// Tiny (0.8 MB/chunk); taps are L1/L2-resident.
// ---------------------------------------------------------------------------
__global__ void __launch_bounds__(256) box_factor_kernel(int b0) {
    const int n = CHUNK_B * HWSZ;
    int i = blockIdx.x * blockDim.x + threadIdx.x;
    if (i >= n) return;

    int lb = i / HWSZ;
    int hw = i - lb * HWSZ;
    int b  = b0 + lb;
    int h  = hw / WW;
    int w  = hw - h * WW;

    const float* __restrict__ s0 = g_sp[0] + (size_t)b * HWSZ;
    const float* __restrict__ s1 = g_sp[1] + (size_t)b * HWSZ;

    float t = 0.f;
#pragma unroll
    for (int dh = -2; dh <= 2; ++dh) {
        int hh = h + dh;
        if ((unsigned)hh >= (unsigned)HH) continue;
        int rowo = hh * WW;
#pragma unroll
        for (int dw = -2; dw <= 2; ++dw) {
            int ww2 = w + dw;
            if ((unsigned)ww2 >= (unsigned)WW) continue;
            t += __ldg(&s0[rowo + ww2]) + __ldg(&s1[rowo + ww2]);
        }
    }
    float base = fmaf(1e-4f, t, 2.0f);        // in [2, ~3.5): log2/exp2 safe
    g_f[(size_t)b * HWSZ + hw] = exp2f(-0.75f * log2f(base));
}

// ---------------------------------------------------------------------------
// Kernel C: out = x * f   (x expected L2-resident from kernel A of same chunk)
// __ldcs on x: read + evict-first (frees L2 for next chunk).
// __stcs on out: streaming store, no L2 pollution.
// ---------------------------------------------------------------------------
__global__ void __launch_bounds__(256) scale_kernel(const float* __restrict__ x,
                                                    float* __restrict__ out,
                                                    int b0) {
    const int n4 = (CHUNK_B * CHW) / 4;
    int i4 = blockIdx.x * blockDim.x + threadIdx.x;
    if (i4 >= n4) return;

    int e   = i4 * 4;
    int lb  = e / CHW;
    int rem = e - lb * CHW;
    int hw  = rem % HWSZ;                    // multiple of 4 (HWSZ % 4 == 0)
    int b   = b0 + lb;

    size_t g4 = (size_t)b0 * (CHW / 4) + i4;
    float4 xv = __ldcs(reinterpret_cast<const float4*>(x) + g4);
    float4 fv = *reinterpret_cast<const float4*>(g_f + (size_t)b * HWSZ + hw);

    float4 o;
    o.x = xv.x * fv.x;
    o.y = xv.y * fv.y;
    o.z = xv.z * fv.z;
    o.w = xv.w * fv.w;
    __stcs(reinterpret_cast<float4*>(out) + g4, o);
}

// ---------------------------------------------------------------------------
extern "C" void kernel_launch(void* const* d_in, const int* in_sizes, int n_in,
                              void* d_out, int out_size) {
    const float* x = (const float*)d_in[0];
    float* out = (float*)d_out;

    const int ta = 256, tb = 256, tc = 256;
    const int ga = ((CHUNK_B * HWSZ) / 4 + ta - 1) / ta;        // 196
    const int gb = (CHUNK_B * HWSZ + tb - 1) / tb;              // 784
    const int gc = ((CHUNK_B * CHW) / 4 + tc - 1) / tc;         // 18816

    for (int chunk = 0; chunk < NCHUNK; ++chunk) {
        int b0 = chunk * CHUNK_B;
        chan_sumsq_kernel<<<dim3(ga, 2), ta>>>(x, b0);
        box_factor_kernel<<<gb, tb>>>(b0);
        scale_kernel<<<gc, tc>>>(x, out, b0);
    }
}